// round 8
// baseline (speedup 1.0000x reference)
#include <cuda_runtime.h>
#include <cuda_fp16.h>
#include <cuda_bf16.h>
#include <cstdint>

// ============================================================================
// VQ quantizer: dual-pipe prefilter — fp16 mma.sync (HMMA, codes 0..383) +
// fp32 FFMA2 scalar (codes 384..511) running concurrently — with per-row
// rigorous error bound and provably-exact fp32 argmin rescue.
// z [N,64] f32, codebook [512,64] f32.
// Outputs (concatenated f32): q_ste [N*64], loss [1], ids [N] (as float).
// ============================================================================

#define D        64
#define KCODES   512
#define NTC      384    // codes handled by tensor path (6 chunks of 64)
#define NSC      128    // codes handled by scalar fp32 path
#define MTILE    128
#define TPB      256
#define GRID_MAX 296    // 2 CTAs/SM x 148 SMs

// smem layout (byte offsets)
#define B_OFF      0        // 384 x 144B fp16 codebook rows (tensor share)
#define CB32_OFF   55296    // 128 x 272B f32 codebook rows (scalar share)
#define A_OFF      90112    // 128 x 144B fp16 z tile
#define C2H_OFF    108544   // 512 f32: 0.5*||c||^2
#define Z2S_OFF    110592   // 128 f32: approx ||z||^2 per tile row
#define KID_OFF    111104   // 128 int
#define CN_OFF     111616   // 1 f32: max ||c||
#define SMEM_TOTAL 111648

__device__ double g_partial[4096];

// ---------------- helpers ----------------
__device__ __forceinline__ void mma_fp16(float* c, const uint32_t* a,
                                         uint32_t b0, uint32_t b1) {
    asm volatile(
        "mma.sync.aligned.m16n8k16.row.col.f32.f16.f16.f32 "
        "{%0,%1,%2,%3}, {%4,%5,%6,%7}, {%8,%9}, {%0,%1,%2,%3};"
        : "+f"(c[0]), "+f"(c[1]), "+f"(c[2]), "+f"(c[3])
        : "r"(a[0]), "r"(a[1]), "r"(a[2]), "r"(a[3]), "r"(b0), "r"(b1));
}

#define FMA_F32X2(d, a, b, c) \
    asm("fma.rn.f32x2 %0, %1, %2, %3;" : "=l"(d) : "l"(a), "l"(b), "l"(c))

// top-3 insert (descending)
__device__ __forceinline__ void ins3(float v, int k, float* tv, int* tk) {
    if (v > tv[2]) {
        if (v > tv[0])      { tv[2]=tv[1]; tk[2]=tk[1]; tv[1]=tv[0]; tk[1]=tk[0]; tv[0]=v; tk[0]=k; }
        else if (v > tv[1]) { tv[2]=tv[1]; tk[2]=tk[1]; tv[1]=v; tk[1]=k; }
        else                { tv[2]=v; tk[2]=k; }
    }
}

// EXACT scorer — replicates round-1 arithmetic (verified rel_err 0.0)
__device__ __forceinline__ float exact_d2(const float4* zr, float z2,
                                          const float* __restrict__ crow) {
    const float4* c4 = (const float4*)crow;
    float4 cv[16];
    #pragma unroll
    for (int i = 0; i < 16; i++) cv[i] = c4[i];
    float c2 = 0.f;
    #pragma unroll
    for (int i = 0; i < 16; i++) {
        c2 += cv[i].x * cv[i].x; c2 += cv[i].y * cv[i].y;
        c2 += cv[i].z * cv[i].z; c2 += cv[i].w * cv[i].w;
    }
    float a0 = 0.f, a1 = 0.f, a2 = 0.f, a3 = 0.f;
    #pragma unroll
    for (int i = 0; i < 16; i++) {
        a0 += zr[i].x * cv[i].x;
        a1 += zr[i].y * cv[i].y;
        a2 += zr[i].z * cv[i].z;
        a3 += zr[i].w * cv[i].w;
    }
    float dot = (a0 + a1) + (a2 + a3);
    return (z2 - 2.0f * dot) + c2;
}

__device__ __forceinline__ float z2_of(const float4* zr) {
    float z2 = 0.f;
    #pragma unroll
    for (int i = 0; i < 16; i++)
        z2 += zr[i].x * zr[i].x + zr[i].y * zr[i].y
            + zr[i].z * zr[i].z + zr[i].w * zr[i].w;
    return z2;
}

// convert 64 f32 -> fp16 row (144B stride), return sum of squares (approx ok)
__device__ __forceinline__ float stage_row_fp16(char* dst, const float4* v) {
    float s = 0.f;
    #pragma unroll
    for (int i = 0; i < 16; i++) {
        float4 a = v[i];
        s += a.x * a.x + a.y * a.y + a.z * a.z + a.w * a.w;
        __half2 h0 = __halves2half2(__float2half_rn(a.x), __float2half_rn(a.y));
        __half2 h1 = __halves2half2(__float2half_rn(a.z), __float2half_rn(a.w));
        uint2 w;
        w.x = *(uint32_t*)&h0;
        w.y = *(uint32_t*)&h1;
        *(uint2*)(dst + i * 8) = w;
    }
    return s;
}

// ============================================================================
// Main kernel: persistent, 2 CTAs/SM, 8 warps, M-tile 128 (1 m16 strip/warp)
// ============================================================================
__global__ __launch_bounds__(TPB, 2)
void vq_mma(const float* __restrict__ z, const float* __restrict__ cb,
            int N, float* __restrict__ q_out, float* __restrict__ ids_out)
{
    extern __shared__ char smem[];
    const int tid  = threadIdx.x;
    const int wid  = tid >> 5;
    const int lane = tid & 31;
    const int qr   = lane >> 2;   // 0..7
    const int qc   = lane & 3;    // 0..3

    float* c2h   = (float*)(smem + C2H_OFF);
    float* z2s   = (float*)(smem + Z2S_OFF);
    int*   kidS  = (int*)(smem + KID_OFF);
    float* cnp   = (float*)(smem + CN_OFF);
    float* cbs32 = (float*)(smem + CB32_OFF);

    // ---- stage codebook once ----
    for (int n = tid; n < KCODES; n += TPB) {
        float4 cv[16];
        const float4* c4 = (const float4*)(cb + (size_t)n * D);
        #pragma unroll
        for (int i = 0; i < 16; i++) cv[i] = c4[i];
        float s = 0.f;
        #pragma unroll
        for (int i = 0; i < 16; i++)
            s += cv[i].x * cv[i].x + cv[i].y * cv[i].y
               + cv[i].z * cv[i].z + cv[i].w * cv[i].w;
        c2h[n] = 0.5f * s;
        if (n < NTC) {
            stage_row_fp16(smem + B_OFF + n * 144, cv);
        } else {
            float4* dst = (float4*)&cbs32[(n - NTC) * 68];
            #pragma unroll
            for (int i = 0; i < 16; i++) dst[i] = cv[i];
        }
    }
    __syncthreads();
    if (tid < 32) {
        float m = 0.f;
        for (int i = tid; i < KCODES; i += 32) m = fmaxf(m, c2h[i]);
        #pragma unroll
        for (int off = 16; off; off >>= 1)
            m = fmaxf(m, __shfl_xor_sync(0xffffffffu, m, off));
        if (tid == 0) *cnp = sqrtf(2.0f * m);
    }
    __syncthreads();
    const float CNMAX = *cnp;

    const int ntiles = N / MTILE;
    double dsum = 0.0;

    for (int tile = blockIdx.x; tile < ntiles; tile += gridDim.x) {
        // ---- stage A tile: threads 0..127 convert one row each ----
        if (tid < MTILE) {
            float4 zr[16];
            const float4* zp = (const float4*)(z + (size_t)(tile * MTILE + tid) * D);
            #pragma unroll
            for (int i = 0; i < 16; i++) zr[i] = zp[i];
            z2s[tid] = stage_row_fp16(smem + A_OFF + tid * 144, zr);
        }
        __syncthreads();

        // ---- A fragments (hoisted; strip rows wid*16+qr, +8) ----
        uint32_t afr[4][4];
        {
            const int r0 = (wid * 16 + qr) * 144;
            #pragma unroll
            for (int ks = 0; ks < 4; ks++) {
                const int kb = ks * 32 + qc * 4;
                afr[ks][0] = *(const uint32_t*)(smem + A_OFF + r0 + kb);
                afr[ks][1] = *(const uint32_t*)(smem + A_OFF + r0 + 8 * 144 + kb);
                afr[ks][2] = *(const uint32_t*)(smem + A_OFF + r0 + kb + 16);
                afr[ks][3] = *(const uint32_t*)(smem + A_OFF + r0 + 8 * 144 + kb + 16);
            }
        }

        // ---- tensor path: codes 0..383, per-thread top-3 for 2 row-slots ----
        float tv[2][3];
        int   tk[2][3];
        #pragma unroll
        for (int s = 0; s < 2; s++) {
            tv[s][0] = tv[s][1] = tv[s][2] = -3.4e38f;
            tk[s][0] = tk[s][1] = tk[s][2] = 0;
        }

        for (int ch = 0; ch < 6; ch++) {       // 6 chunks of 64 codes
            float acc[8][4];
            #pragma unroll
            for (int n8 = 0; n8 < 8; n8++) {   // init acc = -0.5*||c||^2
                const int col0 = ch * 64 + n8 * 8 + qc * 2;
                const float h0 = c2h[col0], h1 = c2h[col0 + 1];
                acc[n8][0] = -h0; acc[n8][1] = -h1;
                acc[n8][2] = -h0; acc[n8][3] = -h1;
            }
            #pragma unroll
            for (int ks = 0; ks < 4; ks++) {
                const int kb = ks * 32 + qc * 4;
                #pragma unroll
                for (int n8 = 0; n8 < 8; n8++) {
                    const int cbyte = (ch * 64 + n8 * 8 + qr) * 144 + kb;
                    uint32_t b0 = *(const uint32_t*)(smem + B_OFF + cbyte);
                    uint32_t b1 = *(const uint32_t*)(smem + B_OFF + cbyte + 16);
                    mma_fp16(acc[n8], afr[ks], b0, b1);
                }
            }
            #pragma unroll
            for (int n8 = 0; n8 < 8; n8++) {
                const int col0 = ch * 64 + n8 * 8 + qc * 2;
                ins3(acc[n8][0], col0,     tv[0], tk[0]);
                ins3(acc[n8][1], col0 + 1, tv[0], tk[0]);
                ins3(acc[n8][2], col0,     tv[1], tk[1]);
                ins3(acc[n8][3], col0 + 1, tv[1], tk[1]);
            }
        }

        const float loc3_0 = tv[0][2];
        const float loc3_1 = tv[1][2];

        // ---- scalar fp32 path: codes 384..511 on the FMA pipe ----
        // lane L handles row wid*16 + (L>>1), k-half (L&1); tracks top-3 over
        // codes of parity (L&1) for that row.
        float stv[3] = {-3.4e38f, -3.4e38f, -3.4e38f};
        int   stk[3] = {0, 0, 0};
        {
            const int khalf = lane & 1;
            const int srow  = wid * 16 + (lane >> 1);
            // load this row's z half (32 f32) packed as 16 f32x2
            unsigned long long zb[16];
            {
                const ulonglong2* zp = (const ulonglong2*)
                    (z + (size_t)(tile * MTILE + srow) * D + khalf * 32);
                #pragma unroll
                for (int i = 0; i < 8; i++) {
                    ulonglong2 v = zp[i];
                    zb[2 * i] = v.x; zb[2 * i + 1] = v.y;
                }
            }
            #pragma unroll 2
            for (int j = 0; j < NSC; j++) {
                const ulonglong2* crow = (const ulonglong2*)
                    &cbs32[j * 68 + khalf * 32];
                unsigned long long p0 = 0ull, p1 = 0ull;
                #pragma unroll
                for (int i = 0; i < 8; i++) {
                    ulonglong2 cv = crow[i];
                    FMA_F32X2(p0, zb[2 * i],     cv.x, p0);
                    FMA_F32X2(p1, zb[2 * i + 1], cv.y, p1);
                }
                float2 q0 = *(float2*)&p0;
                float2 q1 = *(float2*)&p1;
                float part = (q0.x + q0.y) + (q1.x + q1.y);
                float full = part + __shfl_xor_sync(0xffffffffu, part, 1);
                if ((j & 1) == khalf) {
                    float v = full - c2h[NTC + j];
                    ins3(v, NTC + j, stv, stk);
                }
            }
        }
        const float sloc3 = stv[2];

        // ---- quad merge (xor 1, 2) of tensor top-3 ----
        #pragma unroll
        for (int off = 1; off <= 2; off <<= 1) {
            #pragma unroll
            for (int s = 0; s < 2; s++) {
                float sv0 = tv[s][0], sv1 = tv[s][1], sv2 = tv[s][2];
                int   sk0 = tk[s][0], sk1 = tk[s][1], sk2 = tk[s][2];
                float ov0 = __shfl_xor_sync(0xffffffffu, sv0, off);
                float ov1 = __shfl_xor_sync(0xffffffffu, sv1, off);
                float ov2 = __shfl_xor_sync(0xffffffffu, sv2, off);
                int   ok0 = __shfl_xor_sync(0xffffffffu, sk0, off);
                int   ok1 = __shfl_xor_sync(0xffffffffu, sk1, off);
                int   ok2 = __shfl_xor_sync(0xffffffffu, sk2, off);
                ins3(ov0, ok0, tv[s], tk[s]);
                ins3(ov1, ok1, tv[s], tk[s]);
                ins3(ov2, ok2, tv[s], tk[s]);
            }
        }

        // ---- merge scalar top-3 into row slots ----
        // slot0 row = wid*16+qr -> scalar lanes 2*qr, 2*qr+1
        // slot1 row = wid*16+qr+8 -> scalar lanes 16+2*qr, 17+2*qr
        float s0l3a, s0l3b, s1l3a, s1l3b;
        {
            const int l0a = 2 * qr, l0b = 2 * qr + 1;
            const int l1a = 16 + 2 * qr, l1b = 17 + 2 * qr;
            #pragma unroll
            for (int e = 0; e < 3; e++) {
                float v = stv[e]; int k = stk[e];
                float v0a = __shfl_sync(0xffffffffu, v, l0a);
                int   k0a = __shfl_sync(0xffffffffu, k, l0a);
                float v0b = __shfl_sync(0xffffffffu, v, l0b);
                int   k0b = __shfl_sync(0xffffffffu, k, l0b);
                float v1a = __shfl_sync(0xffffffffu, v, l1a);
                int   k1a = __shfl_sync(0xffffffffu, k, l1a);
                float v1b = __shfl_sync(0xffffffffu, v, l1b);
                int   k1b = __shfl_sync(0xffffffffu, k, l1b);
                ins3(v0a, k0a, tv[0], tk[0]);
                ins3(v0b, k0b, tv[0], tk[0]);
                ins3(v1a, k1a, tv[1], tk[1]);
                ins3(v1b, k1b, tv[1], tk[1]);
            }
            s0l3a = __shfl_sync(0xffffffffu, sloc3, l0a);
            s0l3b = __shfl_sync(0xffffffffu, sloc3, l0b);
            s1l3a = __shfl_sync(0xffffffffu, sloc3, l1a);
            s1l3b = __shfl_sync(0xffffffffu, sloc3, l1b);
        }

        // ---- per-row rigorous threshold: 2e <= 2^-9 * ||z|| * ||c||max ----
        const int r0 = wid * 16 + qr;
        const float thr0 = sqrtf(z2s[r0])     * CNMAX * 0.001953125f + 5e-4f;
        const float thr1 = sqrtf(z2s[r0 + 8]) * CNMAX * 0.001953125f + 5e-4f;

        // unsafe if any partition's 3rd-best, or the global 3rd-best, is
        // within thr of the best (-> candidate set could exceed top-2)
        unsigned bal0 = __ballot_sync(0xffffffffu, loc3_0 >= tv[0][0] - thr0);
        unsigned bal1 = __ballot_sync(0xffffffffu, loc3_1 >= tv[1][0] - thr1);
        const unsigned qsh = lane & ~3;
        const bool u0 = (((bal0 >> qsh) & 0xFu) != 0)
                      || (s0l3a >= tv[0][0] - thr0) || (s0l3b >= tv[0][0] - thr0)
                      || (tv[0][2] >= tv[0][0] - thr0);
        const bool u1 = (((bal1 >> qsh) & 0xFu) != 0)
                      || (s1l3a >= tv[1][0] - thr1) || (s1l3b >= tv[1][0] - thr1)
                      || (tv[1][2] >= tv[1][0] - thr1);

        // ---- finalize: lane qc=0 -> slot 0, qc=1 -> slot 1 ----
        const bool mine = (qc < 2);
        const int  myrow = r0 + qc * 8;
        const bool my_unsafe = mine && (qc == 0 ? u0 : u1);
        int kid = 0;

        if (mine && !my_unsafe) {
            float b0v, b1v, myTHR;
            int   k0v, k1v;
            if (qc == 0) { b0v = tv[0][0]; b1v = tv[0][1];
                           k0v = tk[0][0]; k1v = tk[0][1]; myTHR = thr0; }
            else         { b0v = tv[1][0]; b1v = tv[1][1];
                           k0v = tk[1][0]; k1v = tk[1][1]; myTHR = thr1; }
            if (b1v < b0v - myTHR) {
                kid = k0v;                              // margin proves winner
            } else {
                int ka = k0v < k1v ? k0v : k1v;
                int kb = k0v < k1v ? k1v : k0v;
                const int grow = tile * MTILE + myrow;
                float4 zr[16];
                const float4* zp = (const float4*)(z + (size_t)grow * D);
                #pragma unroll
                for (int i = 0; i < 16; i++) zr[i] = zp[i];
                const float z2 = z2_of(zr);
                float da = exact_d2(zr, z2, cb + (size_t)ka * D);
                float db = exact_d2(zr, z2, cb + (size_t)kb * D);
                kid = (db < da) ? kb : ka;              // ascending k, strict <
            }
        }

        // ---- warp-cooperative exact scan for unsafe rows (rare) ----
        unsigned need = __ballot_sync(0xffffffffu, my_unsafe);
        while (need) {
            const int src = __ffs(need) - 1;
            need &= need - 1;
            const int rl = __shfl_sync(0xffffffffu, myrow, src);
            const int grow = tile * MTILE + rl;
            float4 zr[16];
            const float4* zp = (const float4*)(z + (size_t)grow * D);
            #pragma unroll
            for (int i = 0; i < 16; i++) zr[i] = zp[i];
            const float z2 = z2_of(zr);
            float best = 3.402823466e38f; int bk = KCODES;
            for (int k = lane; k < KCODES; k += 32) {
                float d = exact_d2(zr, z2, cb + (size_t)k * D);
                if (d < best) { best = d; bk = k; }
            }
            #pragma unroll
            for (int off = 16; off; off >>= 1) {
                float ob = __shfl_xor_sync(0xffffffffu, best, off);
                int   obk = __shfl_xor_sync(0xffffffffu, bk, off);
                if (ob < best || (ob == best && obk < bk)) { best = ob; bk = obk; }
            }
            if (lane == src) kid = bk;
        }

        if (mine) kidS[myrow] = kid;
        __syncthreads();

        // ---- epilogue: threads 0..127, row tid ----
        if (tid < MTILE) {
            const int grow = tile * MTILE + tid;
            const int k = kidS[tid];
            float4 zr[16];
            const float4* zp = (const float4*)(z + (size_t)grow * D);
            #pragma unroll
            for (int i = 0; i < 16; i++) zr[i] = zp[i];
            const float4* q4 = (const float4*)(cb + (size_t)k * D);
            float4* qo = (float4*)(q_out + (size_t)grow * D);
            float lsum = 0.f;
            #pragma unroll
            for (int i = 0; i < 16; i++) {
                float4 cv = q4[i];
                float4 zv = zr[i];
                float dx = zv.x - cv.x, dy = zv.y - cv.y;
                float dz = zv.z - cv.z, dw = zv.w - cv.w;
                lsum += dx * dx + dy * dy + dz * dz + dw * dw;
                float4 o;
                o.x = zv.x + (cv.x - zv.x);   // fl(z + fl(q - z)), reference STE
                o.y = zv.y + (cv.y - zv.y);
                o.z = zv.z + (cv.z - zv.z);
                o.w = zv.w + (cv.w - zv.w);
                qo[i] = o;
            }
            if (ids_out) ids_out[grow] = (float)k;
            dsum += (double)lsum;
        }
        __syncthreads();
    }

    // ---- deterministic per-CTA loss reduction ----
    double* red = (double*)(smem + B_OFF);   // codebook region reusable now
    red[tid] = dsum;
    __syncthreads();
    if (tid == 0) {
        double s = 0.0;
        for (int i = 0; i < TPB; i++) s += red[i];
        g_partial[blockIdx.x] = s;
    }
}

// ============================================================================
// Generic fallback (round-2 kernel) for unexpected shapes
// ============================================================================
#define FTPB 256
#define ROW_PAD 68
__global__ __launch_bounds__(FTPB) void vq_ref(
    const float* __restrict__ z, const float* __restrict__ cb,
    int N, int K, float* __restrict__ q_out, float* __restrict__ ids_out)
{
    extern __shared__ float fsm[];
    float* cbs = fsm;
    float* c2  = fsm + (size_t)K * ROW_PAD;
    const int tid = threadIdx.x;
    const float4* cb4 = (const float4*)cb;
    const int nvec = K * (D / 4);
    for (int idx = tid; idx < nvec; idx += FTPB) {
        int k = idx >> 4, c = idx & 15;
        *(float4*)&cbs[k * ROW_PAD + c * 4] = cb4[idx];
    }
    __syncthreads();
    for (int k = tid; k < K; k += FTPB) {
        const float* r = &cbs[k * ROW_PAD];
        float s = 0.f;
        #pragma unroll
        for (int i = 0; i < D; i++) s += r[i] * r[i];
        c2[k] = s;
    }
    __syncthreads();
    const int row = blockIdx.x * FTPB + tid;
    float lsum = 0.f;
    if (row < N) {
        float4 zr[16];
        const float4* zp = (const float4*)(z + (size_t)row * D);
        #pragma unroll
        for (int i = 0; i < 16; i++) zr[i] = zp[i];
        float z2 = 0.f;
        #pragma unroll
        for (int i = 0; i < 16; i++)
            z2 += zr[i].x * zr[i].x + zr[i].y * zr[i].y
                + zr[i].z * zr[i].z + zr[i].w * zr[i].w;
        float best = 3.402823466e38f; int bid = 0;
        for (int k = 0; k < K; k++) {
            const float4* crow = (const float4*)&cbs[k * ROW_PAD];
            float a0 = 0.f, a1 = 0.f, a2 = 0.f, a3 = 0.f;
            #pragma unroll
            for (int i = 0; i < 16; i++) {
                float4 cv = crow[i];
                a0 += zr[i].x * cv.x; a1 += zr[i].y * cv.y;
                a2 += zr[i].z * cv.z; a3 += zr[i].w * cv.w;
            }
            float dot = (a0 + a1) + (a2 + a3);
            float d = (z2 - 2.0f * dot) + c2[k];
            if (d < best) { best = d; bid = k; }
        }
        const float4* crow = (const float4*)&cbs[bid * ROW_PAD];
        float4* qo = (float4*)(q_out + (size_t)row * D);
        #pragma unroll
        for (int i = 0; i < 16; i++) {
            float4 cv = crow[i];
            float4 zv = zr[i];
            float dx = zv.x - cv.x, dy = zv.y - cv.y;
            float dz = zv.z - cv.z, dw = zv.w - cv.w;
            lsum += dx * dx + dy * dy + dz * dz + dw * dw;
            float4 o;
            o.x = zv.x + (cv.x - zv.x); o.y = zv.y + (cv.y - zv.y);
            o.z = zv.z + (cv.z - zv.z); o.w = zv.w + (cv.w - zv.w);
            qo[i] = o;
        }
        if (ids_out) ids_out[row] = (float)bid;
    }
    #pragma unroll
    for (int off = 16; off; off >>= 1)
        lsum += __shfl_down_sync(0xffffffffu, lsum, off);
    __shared__ double wp[FTPB / 32];
    if ((tid & 31) == 0) wp[tid >> 5] = (double)lsum;
    __syncthreads();
    if (tid == 0) {
        double s = 0.0;
        #pragma unroll
        for (int w = 0; w < FTPB / 32; w++) s += wp[w];
        g_partial[blockIdx.x] = s;
    }
}

__global__ void vq_finalize(int nblocks, double inv_total, float* loss_out)
{
    __shared__ double sp[256];
    const int tid = threadIdx.x;
    double s = 0.0;
    for (int i = tid; i < nblocks; i += 256) s += g_partial[i];
    sp[tid] = s;
    __syncthreads();
    for (int off = 128; off; off >>= 1) {
        if (tid < off) sp[tid] += sp[tid + off];
        __syncthreads();
    }
    if (tid == 0) {
        double mean = sp[0] * inv_total;
        loss_out[0] = (float)(mean + 0.25 * mean);
    }
}

extern "C" void kernel_launch(void* const* d_in, const int* in_sizes, int n_in,
                              void* d_out, int out_size)
{
    const float* z  = (const float*)d_in[0];
    const float* cb = (const float*)d_in[1];
    const int N = in_sizes[0] / D;
    const int K = in_sizes[1] / D;

    float* out = (float*)d_out;
    float* q_out    = out;
    float* loss_ptr = nullptr;
    float* ids_ptr  = nullptr;
    const long base = (long)N * D;
    if ((long)out_size >= base + 1 + N) { loss_ptr = out + base; ids_ptr = out + base + 1; }
    else if ((long)out_size == base + N) { ids_ptr = out + base; }
    else if ((long)out_size == base + 1) { loss_ptr = out + base; }

    int nblocks;
    if (K == KCODES && (N % MTILE) == 0 && N > 0) {
        const int ntiles = N / MTILE;
        nblocks = ntiles < GRID_MAX ? ntiles : GRID_MAX;
        cudaFuncSetAttribute(vq_mma, cudaFuncAttributeMaxDynamicSharedMemorySize, SMEM_TOTAL);
        vq_mma<<<nblocks, TPB, SMEM_TOTAL>>>(z, cb, N, q_out, ids_ptr);
    } else {
        const size_t smem_bytes = ((size_t)K * ROW_PAD + K) * sizeof(float);
        cudaFuncSetAttribute(vq_ref, cudaFuncAttributeMaxDynamicSharedMemorySize, (int)smem_bytes);
        nblocks = (N + FTPB - 1) / FTPB;
        vq_ref<<<nblocks, FTPB, smem_bytes>>>(z, cb, N, K, q_out, ids_ptr);
    }

    if (loss_ptr) {
        double inv_total = 1.0 / ((double)N * (double)D);
        vq_finalize<<<1, 256>>>(nblocks, inv_total, loss_ptr);
    }
}

// round 9
// speedup vs baseline: 1.1902x; 1.1902x over previous
#include <cuda_runtime.h>
#include <cuda_fp16.h>
#include <cuda_bf16.h>
#include <cstdint>

// ============================================================================
// VQ quantizer: dual-pipe prefilter — fp16 mma.sync (codes 0..319) + int8
// dp4a 3-pass split (codes 320..511) — per-row rigorous error bound,
// provably-exact fp32 argmin rescue.
// z [N,64] f32, codebook [512,64] f32.
// Outputs (concatenated f32): q_ste [N*64], loss [1], ids [N] (as float).
// ============================================================================

#define D        64
#define KCODES   512
#define NTC      320    // tensor codes (5 chunks of 64)
#define NSC      192    // dp4a codes
#define MTILE    128
#define TPB      256
#define GRID_MAX 296    // 2 CTAs/SM x 148 SMs

// smem layout (byte offsets)
#define B_OFF      0        // 320 x 144B fp16 codebook rows
#define CH_OFF     46080    // 192 x 64B int8-hi codebook (16 u32/row)
#define CL_OFF     58368    // 192 x 64B int8-lo
#define A_OFF      70656    // 128 x 144B fp16 z tile
#define C2H_OFF    89088    // 512 f32: 0.5*||c||^2
#define SCS_OFF    91136    // 192 f32: s_c per dp4a code
#define Z2S_OFF    91904    // 128 f32: approx ||z||^2
#define KID_OFF    92416    // 128 int
#define CN_OFF     92928    // 1 f32: max ||c||
#define STOPV_OFF  92944    // 256 x 3 f32: scalar top-3 values
#define STOPK_OFF  96016    // 256 x 3 int: scalar top-3 ids
#define SMEM_TOTAL 99200

__device__ double g_partial[4096];

// ---------------- helpers ----------------
__device__ __forceinline__ void mma_fp16(float* c, const uint32_t* a,
                                         uint32_t b0, uint32_t b1) {
    asm volatile(
        "mma.sync.aligned.m16n8k16.row.col.f32.f16.f16.f32 "
        "{%0,%1,%2,%3}, {%4,%5,%6,%7}, {%8,%9}, {%0,%1,%2,%3};"
        : "+f"(c[0]), "+f"(c[1]), "+f"(c[2]), "+f"(c[3])
        : "r"(a[0]), "r"(a[1]), "r"(a[2]), "r"(a[3]), "r"(b0), "r"(b1));
}

__device__ __forceinline__ void ins3(float v, int k, float* tv, int* tk) {
    if (v > tv[2]) {
        if (v > tv[0])      { tv[2]=tv[1]; tk[2]=tk[1]; tv[1]=tv[0]; tk[1]=tk[0]; tv[0]=v; tk[0]=k; }
        else if (v > tv[1]) { tv[2]=tv[1]; tk[2]=tk[1]; tv[1]=v; tk[1]=k; }
        else                { tv[2]=v; tk[2]=k; }
    }
}

__device__ __forceinline__ uint32_t pack4(int a, int b, int c, int d) {
    return (uint32_t)(a & 0xFF) | ((uint32_t)(b & 0xFF) << 8)
         | ((uint32_t)(c & 0xFF) << 16) | ((uint32_t)(d & 0xFF) << 24);
}

// EXACT scorer — replicates round-1 arithmetic (verified rel_err 0.0)
__device__ __forceinline__ float exact_d2(const float4* zr, float z2,
                                          const float* __restrict__ crow) {
    const float4* c4 = (const float4*)crow;
    float4 cv[16];
    #pragma unroll
    for (int i = 0; i < 16; i++) cv[i] = c4[i];
    float c2 = 0.f;
    #pragma unroll
    for (int i = 0; i < 16; i++) {
        c2 += cv[i].x * cv[i].x; c2 += cv[i].y * cv[i].y;
        c2 += cv[i].z * cv[i].z; c2 += cv[i].w * cv[i].w;
    }
    float a0 = 0.f, a1 = 0.f, a2 = 0.f, a3 = 0.f;
    #pragma unroll
    for (int i = 0; i < 16; i++) {
        a0 += zr[i].x * cv[i].x;
        a1 += zr[i].y * cv[i].y;
        a2 += zr[i].z * cv[i].z;
        a3 += zr[i].w * cv[i].w;
    }
    float dot = (a0 + a1) + (a2 + a3);
    return (z2 - 2.0f * dot) + c2;
}

__device__ __forceinline__ float z2_of(const float4* zr) {
    float z2 = 0.f;
    #pragma unroll
    for (int i = 0; i < 16; i++)
        z2 += zr[i].x * zr[i].x + zr[i].y * zr[i].y
            + zr[i].z * zr[i].z + zr[i].w * zr[i].w;
    return z2;
}

__device__ __forceinline__ float stage_row_fp16(char* dst, const float4* v) {
    float s = 0.f;
    #pragma unroll
    for (int i = 0; i < 16; i++) {
        float4 a = v[i];
        s += a.x * a.x + a.y * a.y + a.z * a.z + a.w * a.w;
        __half2 h0 = __halves2half2(__float2half_rn(a.x), __float2half_rn(a.y));
        __half2 h1 = __halves2half2(__float2half_rn(a.z), __float2half_rn(a.w));
        uint2 w;
        w.x = *(uint32_t*)&h0;
        w.y = *(uint32_t*)&h1;
        *(uint2*)(dst + i * 8) = w;
    }
    return s;
}

// 2-term int8 split of a 64-f32 row: v = s*(hi + lo/128) + resid, |resid|<=s/256
__device__ __forceinline__ void quant_row_s8(const float4* v, float m,
                                             uint32_t* hi, uint32_t* lo,
                                             float& s_out) {
    const float s    = (m > 0.f) ? (m / 127.0f) : 1.0f;
    const float inv  = (m > 0.f) ? (127.0f / m) : 0.0f;
    const float inv2 = inv * 128.0f;
    #pragma unroll
    for (int i = 0; i < 16; i++) {
        float4 a = v[i];
        int h0 = __float2int_rn(a.x * inv);
        int h1 = __float2int_rn(a.y * inv);
        int h2 = __float2int_rn(a.z * inv);
        int h3 = __float2int_rn(a.w * inv);
        int l0 = __float2int_rn((a.x - (float)h0 * s) * inv2);
        int l1 = __float2int_rn((a.y - (float)h1 * s) * inv2);
        int l2 = __float2int_rn((a.z - (float)h2 * s) * inv2);
        int l3 = __float2int_rn((a.w - (float)h3 * s) * inv2);
        hi[i] = pack4(h0, h1, h2, h3);
        lo[i] = pack4(l0, l1, l2, l3);
    }
    s_out = s;
}

// ============================================================================
// Main kernel: persistent, 2 CTAs/SM, 8 warps, M-tile 128
// ============================================================================
__global__ __launch_bounds__(TPB, 2)
void vq_mma(const float* __restrict__ z, const float* __restrict__ cb,
            int N, float* __restrict__ q_out, float* __restrict__ ids_out)
{
    extern __shared__ char smem[];
    const int tid  = threadIdx.x;
    const int wid  = tid >> 5;
    const int lane = tid & 31;
    const int qr   = lane >> 2;
    const int qc   = lane & 3;

    float* c2h   = (float*)(smem + C2H_OFF);
    float* scs   = (float*)(smem + SCS_OFF);
    float* z2s   = (float*)(smem + Z2S_OFF);
    int*   kidS  = (int*)(smem + KID_OFF);
    float* cnp   = (float*)(smem + CN_OFF);
    float* stopv = (float*)(smem + STOPV_OFF);
    int*   stopk = (int*)(smem + STOPK_OFF);

    // ---- stage codebook once ----
    for (int n = tid; n < KCODES; n += TPB) {
        float4 cv[16];
        const float4* c4 = (const float4*)(cb + (size_t)n * D);
        #pragma unroll
        for (int i = 0; i < 16; i++) cv[i] = c4[i];
        float s = 0.f, m = 0.f;
        #pragma unroll
        for (int i = 0; i < 16; i++) {
            s += cv[i].x * cv[i].x + cv[i].y * cv[i].y
               + cv[i].z * cv[i].z + cv[i].w * cv[i].w;
            m = fmaxf(m, fmaxf(fmaxf(fabsf(cv[i].x), fabsf(cv[i].y)),
                               fmaxf(fabsf(cv[i].z), fabsf(cv[i].w))));
        }
        c2h[n] = 0.5f * s;
        if (n < NTC) {
            stage_row_fp16(smem + B_OFF + n * 144, cv);
        } else {
            uint32_t hi[16], lo[16]; float sc;
            quant_row_s8(cv, m, hi, lo, sc);
            scs[n - NTC] = sc;
            uint4* hd = (uint4*)(smem + CH_OFF + (n - NTC) * 64);
            uint4* ld = (uint4*)(smem + CL_OFF + (n - NTC) * 64);
            #pragma unroll
            for (int i = 0; i < 4; i++) {
                hd[i] = make_uint4(hi[4*i], hi[4*i+1], hi[4*i+2], hi[4*i+3]);
                ld[i] = make_uint4(lo[4*i], lo[4*i+1], lo[4*i+2], lo[4*i+3]);
            }
        }
    }
    __syncthreads();
    if (tid < 32) {
        float m = 0.f;
        for (int i = tid; i < KCODES; i += 32) m = fmaxf(m, c2h[i]);
        #pragma unroll
        for (int off = 16; off; off >>= 1)
            m = fmaxf(m, __shfl_xor_sync(0xffffffffu, m, off));
        if (tid == 0) *cnp = sqrtf(2.0f * m);
    }
    __syncthreads();
    const float CNMAX = *cnp;

    const int ntiles = N / MTILE;
    double dsum = 0.0;

    for (int tile = blockIdx.x; tile < ntiles; tile += gridDim.x) {
        // ---- stage A tile ----
        if (tid < MTILE) {
            float4 zr[16];
            const float4* zp = (const float4*)(z + (size_t)(tile * MTILE + tid) * D);
            #pragma unroll
            for (int i = 0; i < 16; i++) zr[i] = zp[i];
            z2s[tid] = stage_row_fp16(smem + A_OFF + tid * 144, zr);
        }
        __syncthreads();

        float tv[2][3];
        int   tk[2][3];
        #pragma unroll
        for (int s = 0; s < 2; s++) {
            tv[s][0] = tv[s][1] = tv[s][2] = -3.4e38f;
            tk[s][0] = tk[s][1] = tk[s][2] = 0;
        }

        // -------- tensor phase: codes 0..319 --------
        auto tensor_phase = [&]() {
            uint32_t afr[4][4];
            const int r0b = (wid * 16 + qr) * 144;
            #pragma unroll
            for (int ks = 0; ks < 4; ks++) {
                const int kb = ks * 32 + qc * 4;
                afr[ks][0] = *(const uint32_t*)(smem + A_OFF + r0b + kb);
                afr[ks][1] = *(const uint32_t*)(smem + A_OFF + r0b + 8 * 144 + kb);
                afr[ks][2] = *(const uint32_t*)(smem + A_OFF + r0b + kb + 16);
                afr[ks][3] = *(const uint32_t*)(smem + A_OFF + r0b + 8 * 144 + kb + 16);
            }
            for (int ch = 0; ch < 5; ch++) {
                float acc[8][4];
                #pragma unroll
                for (int n8 = 0; n8 < 8; n8++) {    // acc init = -0.5*||c||^2
                    const int col0 = ch * 64 + n8 * 8 + qc * 2;
                    const float h0 = c2h[col0], h1 = c2h[col0 + 1];
                    acc[n8][0] = -h0; acc[n8][1] = -h1;
                    acc[n8][2] = -h0; acc[n8][3] = -h1;
                }
                #pragma unroll
                for (int ks = 0; ks < 4; ks++) {
                    const int kb = ks * 32 + qc * 4;
                    #pragma unroll
                    for (int n8 = 0; n8 < 8; n8++) {
                        const int cbyte = (ch * 64 + n8 * 8 + qr) * 144 + kb;
                        uint32_t b0 = *(const uint32_t*)(smem + B_OFF + cbyte);
                        uint32_t b1 = *(const uint32_t*)(smem + B_OFF + cbyte + 16);
                        mma_fp16(acc[n8], afr[ks], b0, b1);
                    }
                }
                #pragma unroll
                for (int n8 = 0; n8 < 8; n8++) {
                    const int col0 = ch * 64 + n8 * 8 + qc * 2;
                    ins3(acc[n8][0], col0,     tv[0], tk[0]);
                    ins3(acc[n8][1], col0 + 1, tv[0], tk[0]);
                    ins3(acc[n8][2], col0,     tv[1], tk[1]);
                    ins3(acc[n8][3], col0 + 1, tv[1], tk[1]);
                }
            }
        };

        // -------- dp4a phase: codes 320..511 (96 per thread, row tid&127) ----
        auto scalar_phase = [&]() {
            const int srow  = tid & 127;
            const int cbase = (tid < 128) ? 0 : 96;
            float4 zr[16];
            const float4* zp = (const float4*)(z + (size_t)(tile * MTILE + srow) * D);
            #pragma unroll
            for (int i = 0; i < 16; i++) zr[i] = zp[i];
            float m = 0.f;
            #pragma unroll
            for (int i = 0; i < 16; i++)
                m = fmaxf(m, fmaxf(fmaxf(fabsf(zr[i].x), fabsf(zr[i].y)),
                                   fmaxf(fabsf(zr[i].z), fabsf(zr[i].w))));
            uint32_t zh[16], zl[16]; float sz;
            quant_row_s8(zr, m, zh, zl, sz);

            float stv[3] = {-3.4e38f, -3.4e38f, -3.4e38f};
            int   stk[3] = {0, 0, 0};
            for (int j = 0; j < 96; j++) {
                const int code = cbase + j;
                const uint4* chp = (const uint4*)(smem + CH_OFF + code * 64);
                const uint4* clp = (const uint4*)(smem + CL_OFF + code * 64);
                int d0 = 0, d1 = 0, d2 = 0;
                #pragma unroll
                for (int i = 0; i < 4; i++) {
                    uint4 c4h = chp[i], c4l = clp[i];
                    d0 = __dp4a((int)zh[4*i],   (int)c4h.x, d0);
                    d1 = __dp4a((int)zh[4*i],   (int)c4l.x, d1);
                    d2 = __dp4a((int)zl[4*i],   (int)c4h.x, d2);
                    d0 = __dp4a((int)zh[4*i+1], (int)c4h.y, d0);
                    d1 = __dp4a((int)zh[4*i+1], (int)c4l.y, d1);
                    d2 = __dp4a((int)zl[4*i+1], (int)c4h.y, d2);
                    d0 = __dp4a((int)zh[4*i+2], (int)c4h.z, d0);
                    d1 = __dp4a((int)zh[4*i+2], (int)c4l.z, d1);
                    d2 = __dp4a((int)zl[4*i+2], (int)c4h.z, d2);
                    d0 = __dp4a((int)zh[4*i+3], (int)c4h.w, d0);
                    d1 = __dp4a((int)zh[4*i+3], (int)c4l.w, d1);
                    d2 = __dp4a((int)zl[4*i+3], (int)c4h.w, d2);
                }
                float f0  = __int2float_rn(d0);
                float f12 = __int2float_rn(d1 + d2);
                float dot = fmaf(f12, 0.0078125f, f0) * (sz * scs[code]);
                ins3(dot - c2h[NTC + code], NTC + code, stv, stk);
            }
            #pragma unroll
            for (int e = 0; e < 3; e++) {
                stopv[tid * 3 + e] = stv[e];
                stopk[tid * 3 + e] = stk[e];
            }
        };

        if (wid < 4) { tensor_phase(); scalar_phase(); }
        else         { scalar_phase(); tensor_phase(); }

        const float loc3_0 = tv[0][2];
        const float loc3_1 = tv[1][2];
        __syncthreads();   // stopv/stopk visible

        // ---- quad merge (xor 1, 2) of tensor top-3 ----
        #pragma unroll
        for (int off = 1; off <= 2; off <<= 1) {
            #pragma unroll
            for (int s = 0; s < 2; s++) {
                float sv0 = tv[s][0], sv1 = tv[s][1], sv2 = tv[s][2];
                int   sk0 = tk[s][0], sk1 = tk[s][1], sk2 = tk[s][2];
                float ov0 = __shfl_xor_sync(0xffffffffu, sv0, off);
                float ov1 = __shfl_xor_sync(0xffffffffu, sv1, off);
                float ov2 = __shfl_xor_sync(0xffffffffu, sv2, off);
                int   ok0 = __shfl_xor_sync(0xffffffffu, sk0, off);
                int   ok1 = __shfl_xor_sync(0xffffffffu, sk1, off);
                int   ok2 = __shfl_xor_sync(0xffffffffu, sk2, off);
                ins3(ov0, ok0, tv[s], tk[s]);
                ins3(ov1, ok1, tv[s], tk[s]);
                ins3(ov2, ok2, tv[s], tk[s]);
            }
        }

        // per-row rigorous threshold (covers fp16 2^-9 and int8-split bounds)
        const int r0 = wid * 16 + qr;
        const float thr0 = sqrtf(z2s[r0])     * CNMAX * 0.001953125f + 5e-4f;
        const float thr1 = sqrtf(z2s[r0 + 8]) * CNMAX * 0.001953125f + 5e-4f;

        // tensor-partition coverage ballot (vs pre-scalar-merge best: conservative)
        unsigned bal0 = __ballot_sync(0xffffffffu, loc3_0 >= tv[0][0] - thr0);
        unsigned bal1 = __ballot_sync(0xffffffffu, loc3_1 >= tv[1][0] - thr1);
        const unsigned qsh = lane & ~3;

        const bool mine  = (qc < 2);
        const int  myrow = r0 + qc * 8;
        bool my_unsafe = false;
        int  kid = 0;

        if (mine) {
            float* tvS = tv[qc];
            int*   tkS = tk[qc];
            const float myTHR = (qc == 0) ? thr0 : thr1;
            // merge scalar top-3 (both owner threads of this row)
            const int t0 = myrow, t1 = 128 + myrow;
            float s3a = stopv[t0 * 3 + 2];
            float s3b = stopv[t1 * 3 + 2];
            #pragma unroll
            for (int e = 0; e < 3; e++) {
                ins3(stopv[t0 * 3 + e], stopk[t0 * 3 + e], tvS, tkS);
                ins3(stopv[t1 * 3 + e], stopk[t1 * 3 + e], tvS, tkS);
            }
            const float b1 = tvS[0];
            const unsigned tb = ((qc == 0 ? bal0 : bal1) >> qsh) & 0xFu;
            my_unsafe = (tb != 0)
                      || (s3a >= b1 - myTHR) || (s3b >= b1 - myTHR)
                      || (tvS[2] >= b1 - myTHR);

            if (!my_unsafe) {
                if (tvS[1] < b1 - myTHR) {
                    kid = tkS[0];                       // margin proves winner
                } else {
                    int ka = tkS[0] < tkS[1] ? tkS[0] : tkS[1];
                    int kb = tkS[0] < tkS[1] ? tkS[1] : tkS[0];
                    const int grow = tile * MTILE + myrow;
                    float4 zr[16];
                    const float4* zp = (const float4*)(z + (size_t)grow * D);
                    #pragma unroll
                    for (int i = 0; i < 16; i++) zr[i] = zp[i];
                    const float z2 = z2_of(zr);
                    float da = exact_d2(zr, z2, cb + (size_t)ka * D);
                    float db = exact_d2(zr, z2, cb + (size_t)kb * D);
                    kid = (db < da) ? kb : ka;          // ascending k, strict <
                }
            }
        }

        // warp-cooperative exact scan for unsafe rows (rare)
        unsigned need = __ballot_sync(0xffffffffu, my_unsafe);
        while (need) {
            const int src = __ffs(need) - 1;
            need &= need - 1;
            const int rl = __shfl_sync(0xffffffffu, myrow, src);
            const int grow = tile * MTILE + rl;
            float4 zr[16];
            const float4* zp = (const float4*)(z + (size_t)grow * D);
            #pragma unroll
            for (int i = 0; i < 16; i++) zr[i] = zp[i];
            const float z2 = z2_of(zr);
            float best = 3.402823466e38f; int bk = KCODES;
            for (int k = lane; k < KCODES; k += 32) {
                float d = exact_d2(zr, z2, cb + (size_t)k * D);
                if (d < best) { best = d; bk = k; }
            }
            #pragma unroll
            for (int off = 16; off; off >>= 1) {
                float ob = __shfl_xor_sync(0xffffffffu, best, off);
                int   obk = __shfl_xor_sync(0xffffffffu, bk, off);
                if (ob < best || (ob == best && obk < bk)) { best = ob; bk = obk; }
            }
            if (lane == src) kid = bk;
        }

        if (mine) kidS[myrow] = kid;
        __syncthreads();

        // ---- epilogue: threads 0..127, row tid ----
        if (tid < MTILE) {
            const int grow = tile * MTILE + tid;
            const int k = kidS[tid];
            float4 zr[16];
            const float4* zp = (const float4*)(z + (size_t)grow * D);
            #pragma unroll
            for (int i = 0; i < 16; i++) zr[i] = zp[i];
            const float4* q4 = (const float4*)(cb + (size_t)k * D);
            float4* qo = (float4*)(q_out + (size_t)grow * D);
            float lsum = 0.f;
            #pragma unroll
            for (int i = 0; i < 16; i++) {
                float4 cv = q4[i];
                float4 zv = zr[i];
                float dx = zv.x - cv.x, dy = zv.y - cv.y;
                float dz = zv.z - cv.z, dw = zv.w - cv.w;
                lsum += dx * dx + dy * dy + dz * dz + dw * dw;
                float4 o;
                o.x = zv.x + (cv.x - zv.x);   // fl(z + fl(q - z)), reference STE
                o.y = zv.y + (cv.y - zv.y);
                o.z = zv.z + (cv.z - zv.z);
                o.w = zv.w + (cv.w - zv.w);
                qo[i] = o;
            }
            if (ids_out) ids_out[grow] = (float)k;
            dsum += (double)lsum;
        }
        __syncthreads();
    }

    // ---- deterministic per-CTA loss reduction ----
    double* red = (double*)(smem + B_OFF);
    red[tid] = dsum;
    __syncthreads();
    if (tid == 0) {
        double s = 0.0;
        for (int i = 0; i < TPB; i++) s += red[i];
        g_partial[blockIdx.x] = s;
    }
}

// ============================================================================
// Generic fallback (round-2 kernel) for unexpected shapes
// ============================================================================
#define FTPB 256
#define ROW_PAD 68
__global__ __launch_bounds__(FTPB) void vq_ref(
    const float* __restrict__ z, const float* __restrict__ cb,
    int N, int K, float* __restrict__ q_out, float* __restrict__ ids_out)
{
    extern __shared__ float fsm[];
    float* cbs = fsm;
    float* c2  = fsm + (size_t)K * ROW_PAD;
    const int tid = threadIdx.x;
    const float4* cb4 = (const float4*)cb;
    const int nvec = K * (D / 4);
    for (int idx = tid; idx < nvec; idx += FTPB) {
        int k = idx >> 4, c = idx & 15;
        *(float4*)&cbs[k * ROW_PAD + c * 4] = cb4[idx];
    }
    __syncthreads();
    for (int k = tid; k < K; k += FTPB) {
        const float* r = &cbs[k * ROW_PAD];
        float s = 0.f;
        #pragma unroll
        for (int i = 0; i < D; i++) s += r[i] * r[i];
        c2[k] = s;
    }
    __syncthreads();
    const int row = blockIdx.x * FTPB + tid;
    float lsum = 0.f;
    if (row < N) {
        float4 zr[16];
        const float4* zp = (const float4*)(z + (size_t)row * D);
        #pragma unroll
        for (int i = 0; i < 16; i++) zr[i] = zp[i];
        float z2 = 0.f;
        #pragma unroll
        for (int i = 0; i < 16; i++)
            z2 += zr[i].x * zr[i].x + zr[i].y * zr[i].y
                + zr[i].z * zr[i].z + zr[i].w * zr[i].w;
        float best = 3.402823466e38f; int bid = 0;
        for (int k = 0; k < K; k++) {
            const float4* crow = (const float4*)&cbs[k * ROW_PAD];
            float a0 = 0.f, a1 = 0.f, a2 = 0.f, a3 = 0.f;
            #pragma unroll
            for (int i = 0; i < 16; i++) {
                float4 cv = crow[i];
                a0 += zr[i].x * cv.x; a1 += zr[i].y * cv.y;
                a2 += zr[i].z * cv.z; a3 += zr[i].w * cv.w;
            }
            float dot = (a0 + a1) + (a2 + a3);
            float d = (z2 - 2.0f * dot) + c2[k];
            if (d < best) { best = d; bid = k; }
        }
        const float4* crow = (const float4*)&cbs[bid * ROW_PAD];
        float4* qo = (float4*)(q_out + (size_t)row * D);
        #pragma unroll
        for (int i = 0; i < 16; i++) {
            float4 cv = crow[i];
            float4 zv = zr[i];
            float dx = zv.x - cv.x, dy = zv.y - cv.y;
            float dz = zv.z - cv.z, dw = zv.w - cv.w;
            lsum += dx * dx + dy * dy + dz * dz + dw * dw;
            float4 o;
            o.x = zv.x + (cv.x - zv.x); o.y = zv.y + (cv.y - zv.y);
            o.z = zv.z + (cv.z - zv.z); o.w = zv.w + (cv.w - zv.w);
            qo[i] = o;
        }
        if (ids_out) ids_out[row] = (float)bid;
    }
    #pragma unroll
    for (int off = 16; off; off >>= 1)
        lsum += __shfl_down_sync(0xffffffffu, lsum, off);
    __shared__ double wp[FTPB / 32];
    if ((tid & 31) == 0) wp[tid >> 5] = (double)lsum;
    __syncthreads();
    if (tid == 0) {
        double s = 0.0;
        #pragma unroll
        for (int w = 0; w < FTPB / 32; w++) s += wp[w];
        g_partial[blockIdx.x] = s;
    }
}

__global__ void vq_finalize(int nblocks, double inv_total, float* loss_out)
{
    __shared__ double sp[256];
    const int tid = threadIdx.x;
    double s = 0.0;
    for (int i = tid; i < nblocks; i += 256) s += g_partial[i];
    sp[tid] = s;
    __syncthreads();
    for (int off = 128; off; off >>= 1) {
        if (tid < off) sp[tid] += sp[tid + off];
        __syncthreads();
    }
    if (tid == 0) {
        double mean = sp[0] * inv_total;
        loss_out[0] = (float)(mean + 0.25 * mean);
    }
}

extern "C" void kernel_launch(void* const* d_in, const int* in_sizes, int n_in,
                              void* d_out, int out_size)
{
    const float* z  = (const float*)d_in[0];
    const float* cb = (const float*)d_in[1];
    const int N = in_sizes[0] / D;
    const int K = in_sizes[1] / D;

    float* out = (float*)d_out;
    float* q_out    = out;
    float* loss_ptr = nullptr;
    float* ids_ptr  = nullptr;
    const long base = (long)N * D;
    if ((long)out_size >= base + 1 + N) { loss_ptr = out + base; ids_ptr = out + base + 1; }
    else if ((long)out_size == base + N) { ids_ptr = out + base; }
    else if ((long)out_size == base + 1) { loss_ptr = out + base; }

    int nblocks;
    if (K == KCODES && (N % MTILE) == 0 && N > 0) {
        const int ntiles = N / MTILE;
        nblocks = ntiles < GRID_MAX ? ntiles : GRID_MAX;
        cudaFuncSetAttribute(vq_mma, cudaFuncAttributeMaxDynamicSharedMemorySize, SMEM_TOTAL);
        vq_mma<<<nblocks, TPB, SMEM_TOTAL>>>(z, cb, N, q_out, ids_ptr);
    } else {
        const size_t smem_bytes = ((size_t)K * ROW_PAD + K) * sizeof(float);
        cudaFuncSetAttribute(vq_ref, cudaFuncAttributeMaxDynamicSharedMemorySize, (int)smem_bytes);
        nblocks = (N + FTPB - 1) / FTPB;
        vq_ref<<<nblocks, FTPB, smem_bytes>>>(z, cb, N, K, q_out, ids_ptr);
    }

    if (loss_ptr) {
        double inv_total = 1.0 / ((double)N * (double)D);
        vq_finalize<<<1, 256>>>(nblocks, inv_total, loss_ptr);
    }
}

// round 10
// speedup vs baseline: 2.1369x; 1.7954x over previous
#include <cuda_runtime.h>
#include <cuda_fp16.h>
#include <cuda_bf16.h>
#include <cstdint>

// ============================================================================
// VQ quantizer: single-pass fp16 mma.sync prefilter (per-row rigorous error
// bound) + provably-exact fp32 argmin rescue.  R9: epilogue(t) overlapped with
// staging(t+1) via half-block specialization; 2 syncs/tile instead of 3.
// z [N,64] f32, codebook [512,64] f32.
// Outputs (concatenated f32): q_ste [N*64], loss [1], ids [N] (as float).
// ============================================================================

#define D        64
#define KCODES   512
#define MTILE    128
#define TPB      256
#define GRID_MAX 296   // 2 CTAs/SM x 148 SMs

// smem layout (byte offsets); fp16 rows strided 144B => conflict-free frags
#define B_OFF      0        // 512 x 144B fp16 codebook (k-contiguous rows)
#define A_OFF      73728    // 128 x 144B fp16 z tile
#define C2H_OFF    92160    // 512 f32: 0.5*||c||^2
#define Z2S_OFF    94208    // 128 f32: approx ||z||^2 per tile row
#define KID_OFF    94720    // 128 int
#define CN_OFF     95232    // 1 f32: max ||c||
#define SMEM_TOTAL 95744

__device__ double g_partial[4096];

// ---------------- helpers ----------------
__device__ __forceinline__ void mma_fp16(float* c, const uint32_t* a,
                                         uint32_t b0, uint32_t b1) {
    asm volatile(
        "mma.sync.aligned.m16n8k16.row.col.f32.f16.f16.f32 "
        "{%0,%1,%2,%3}, {%4,%5,%6,%7}, {%8,%9}, {%0,%1,%2,%3};"
        : "+f"(c[0]), "+f"(c[1]), "+f"(c[2]), "+f"(c[3])
        : "r"(a[0]), "r"(a[1]), "r"(a[2]), "r"(a[3]), "r"(b0), "r"(b1));
}

// top-3 insert (descending)
__device__ __forceinline__ void ins3(float v, int k, float* tv, int* tk) {
    if (v > tv[2]) {
        if (v > tv[0])      { tv[2]=tv[1]; tk[2]=tk[1]; tv[1]=tv[0]; tk[1]=tk[0]; tv[0]=v; tk[0]=k; }
        else if (v > tv[1]) { tv[2]=tv[1]; tk[2]=tk[1]; tv[1]=v; tk[1]=k; }
        else                { tv[2]=v; tk[2]=k; }
    }
}

// EXACT scorer — replicates round-1 arithmetic (verified rel_err 0.0)
__device__ __forceinline__ float exact_d2(const float4* zr, float z2,
                                          const float* __restrict__ crow) {
    const float4* c4 = (const float4*)crow;
    float4 cv[16];
    #pragma unroll
    for (int i = 0; i < 16; i++) cv[i] = c4[i];
    float c2 = 0.f;
    #pragma unroll
    for (int i = 0; i < 16; i++) {
        c2 += cv[i].x * cv[i].x; c2 += cv[i].y * cv[i].y;
        c2 += cv[i].z * cv[i].z; c2 += cv[i].w * cv[i].w;
    }
    float a0 = 0.f, a1 = 0.f, a2 = 0.f, a3 = 0.f;
    #pragma unroll
    for (int i = 0; i < 16; i++) {
        a0 += zr[i].x * cv[i].x;
        a1 += zr[i].y * cv[i].y;
        a2 += zr[i].z * cv[i].z;
        a3 += zr[i].w * cv[i].w;
    }
    float dot = (a0 + a1) + (a2 + a3);
    return (z2 - 2.0f * dot) + c2;
}

__device__ __forceinline__ float z2_of(const float4* zr) {
    float z2 = 0.f;
    #pragma unroll
    for (int i = 0; i < 16; i++)
        z2 += zr[i].x * zr[i].x + zr[i].y * zr[i].y
            + zr[i].z * zr[i].z + zr[i].w * zr[i].w;
    return z2;
}

// convert 64 f32 -> fp16 row (144B stride), return sum of squares (approx ok)
__device__ __forceinline__ float stage_row_fp16(char* dst, const float4* v) {
    float s = 0.f;
    #pragma unroll
    for (int i = 0; i < 16; i++) {
        float4 a = v[i];
        s += a.x * a.x + a.y * a.y + a.z * a.z + a.w * a.w;
        __half2 h0 = __halves2half2(__float2half_rn(a.x), __float2half_rn(a.y));
        __half2 h1 = __halves2half2(__float2half_rn(a.z), __float2half_rn(a.w));
        uint2 w;
        w.x = *(uint32_t*)&h0;
        w.y = *(uint32_t*)&h1;
        *(uint2*)(dst + i * 8) = w;
    }
    return s;
}

// ============================================================================
// Main kernel: persistent, 2 CTAs/SM, 8 warps, M-tile 128 (1 m16 strip/warp)
// Pipelined: threads 0..127 stage tile t+1 while threads 128..255 run the
// epilogue of tile t.
// ============================================================================
__global__ __launch_bounds__(TPB, 2)
void vq_mma(const float* __restrict__ z, const float* __restrict__ cb,
            int N, float* __restrict__ q_out, float* __restrict__ ids_out)
{
    extern __shared__ char smem[];
    const int tid  = threadIdx.x;
    const int wid  = tid >> 5;
    const int lane = tid & 31;
    const int qr   = lane >> 2;   // 0..7
    const int qc   = lane & 3;    // 0..3

    float* c2h  = (float*)(smem + C2H_OFF);
    float* z2s  = (float*)(smem + Z2S_OFF);
    int*   kidS = (int*)(smem + KID_OFF);
    float* cnp  = (float*)(smem + CN_OFF);

    // ---- stage codebook once: fp16 rows + 0.5*||c||^2 ----
    for (int n = tid; n < KCODES; n += TPB) {
        float4 cv[16];
        const float4* c4 = (const float4*)(cb + (size_t)n * D);
        #pragma unroll
        for (int i = 0; i < 16; i++) cv[i] = c4[i];
        float s = stage_row_fp16(smem + B_OFF + n * 144, cv);
        c2h[n] = 0.5f * s;
    }
    __syncthreads();
    if (tid < 32) {
        float m = 0.f;
        for (int i = tid; i < KCODES; i += 32) m = fmaxf(m, c2h[i]);
        #pragma unroll
        for (int off = 16; off; off >>= 1)
            m = fmaxf(m, __shfl_xor_sync(0xffffffffu, m, off));
        if (tid == 0) *cnp = sqrtf(2.0f * m);
    }
    __syncthreads();
    const float CNMAX = *cnp;

    const int ntiles = N / MTILE;
    double dsum = 0.0;

    // ---- prologue: stage first tile ----
    if (blockIdx.x < ntiles && tid < MTILE) {
        float4 zr[16];
        const float4* zp = (const float4*)(z + (size_t)(blockIdx.x * MTILE + tid) * D);
        #pragma unroll
        for (int i = 0; i < 16; i++) zr[i] = zp[i];
        z2s[tid] = stage_row_fp16(smem + A_OFF + tid * 144, zr);
    }

    for (int tile = blockIdx.x; tile < ntiles; tile += gridDim.x) {
        __syncthreads();   // A(tile)/z2s(tile) visible; prev epilogue done

        // ---- A fragments (hoisted; strip rows wid*16+qr, +8) ----
        uint32_t afr[4][4];
        {
            const int r0b = (wid * 16 + qr) * 144;
            #pragma unroll
            for (int ks = 0; ks < 4; ks++) {
                const int kb = ks * 32 + qc * 4;
                afr[ks][0] = *(const uint32_t*)(smem + A_OFF + r0b + kb);
                afr[ks][1] = *(const uint32_t*)(smem + A_OFF + r0b + 8 * 144 + kb);
                afr[ks][2] = *(const uint32_t*)(smem + A_OFF + r0b + kb + 16);
                afr[ks][3] = *(const uint32_t*)(smem + A_OFF + r0b + 8 * 144 + kb + 16);
            }
        }

        // ---- MMA + per-thread top-3 for 2 row-slots ----
        float tv[2][3];
        int   tk[2][3];
        #pragma unroll
        for (int s = 0; s < 2; s++) {
            tv[s][0] = tv[s][1] = tv[s][2] = -3.4e38f;
            tk[s][0] = tk[s][1] = tk[s][2] = 0;
        }

        for (int ch = 0; ch < 8; ch++) {       // 8 chunks of 64 codes
            float acc[8][4];
            #pragma unroll
            for (int n8 = 0; n8 < 8; n8++) {   // init acc = -0.5*||c||^2
                const int col0 = ch * 64 + n8 * 8 + qc * 2;
                const float h0 = c2h[col0], h1 = c2h[col0 + 1];
                acc[n8][0] = -h0; acc[n8][1] = -h1;
                acc[n8][2] = -h0; acc[n8][3] = -h1;
            }
            #pragma unroll
            for (int ks = 0; ks < 4; ks++) {
                const int kb = ks * 32 + qc * 4;
                #pragma unroll
                for (int n8 = 0; n8 < 8; n8++) {
                    const int cbyte = (ch * 64 + n8 * 8 + qr) * 144 + kb;
                    uint32_t b0 = *(const uint32_t*)(smem + B_OFF + cbyte);
                    uint32_t b1 = *(const uint32_t*)(smem + B_OFF + cbyte + 16);
                    mma_fp16(acc[n8], afr[ks], b0, b1);
                }
            }
            #pragma unroll
            for (int n8 = 0; n8 < 8; n8++) {
                const int col0 = ch * 64 + n8 * 8 + qc * 2;
                ins3(acc[n8][0], col0,     tv[0], tk[0]);
                ins3(acc[n8][1], col0 + 1, tv[0], tk[0]);
                ins3(acc[n8][2], col0,     tv[1], tk[1]);
                ins3(acc[n8][3], col0 + 1, tv[1], tk[1]);
            }
        }

        const float loc3_0 = tv[0][2];
        const float loc3_1 = tv[1][2];

        // ---- quad merge (xor 1, 2) -> global top-3 per slot ----
        #pragma unroll
        for (int off = 1; off <= 2; off <<= 1) {
            #pragma unroll
            for (int s = 0; s < 2; s++) {
                float sv0 = tv[s][0], sv1 = tv[s][1], sv2 = tv[s][2];
                int   sk0 = tk[s][0], sk1 = tk[s][1], sk2 = tk[s][2];
                float ov0 = __shfl_xor_sync(0xffffffffu, sv0, off);
                float ov1 = __shfl_xor_sync(0xffffffffu, sv1, off);
                float ov2 = __shfl_xor_sync(0xffffffffu, sv2, off);
                int   ok0 = __shfl_xor_sync(0xffffffffu, sk0, off);
                int   ok1 = __shfl_xor_sync(0xffffffffu, sk1, off);
                int   ok2 = __shfl_xor_sync(0xffffffffu, sk2, off);
                ins3(ov0, ok0, tv[s], tk[s]);
                ins3(ov1, ok1, tv[s], tk[s]);
                ins3(ov2, ok2, tv[s], tk[s]);
            }
        }

        // ---- per-row rigorous threshold: 2e <= 2^-9 * ||z|| * ||c||max ----
        const int r0 = wid * 16 + qr;
        const float thr0 = sqrtf(z2s[r0])     * CNMAX * 0.001953125f + 5e-4f;
        const float thr1 = sqrtf(z2s[r0 + 8]) * CNMAX * 0.001953125f + 5e-4f;

        unsigned bal0 = __ballot_sync(0xffffffffu, loc3_0 >= tv[0][0] - thr0);
        unsigned bal1 = __ballot_sync(0xffffffffu, loc3_1 >= tv[1][0] - thr1);
        const unsigned qsh = lane & ~3;
        const bool u0 = ((bal0 >> qsh) & 0xFu) != 0;
        const bool u1 = ((bal1 >> qsh) & 0xFu) != 0;

        // ---- finalize: lane qc=0 -> slot 0, qc=1 -> slot 1 ----
        const bool mine = (qc < 2);
        const int  myrow = r0 + qc * 8;                 // valid when mine
        const bool my_unsafe = mine && (qc == 0 ? u0 : u1);
        int kid = 0;

        if (mine && !my_unsafe) {
            float b0v, b1v, b2v, myTHR;
            int   k0v, k1v, k2v;
            if (qc == 0) { b0v=tv[0][0]; b1v=tv[0][1]; b2v=tv[0][2];
                           k0v=tk[0][0]; k1v=tk[0][1]; k2v=tk[0][2]; myTHR=thr0; }
            else         { b0v=tv[1][0]; b1v=tv[1][1]; b2v=tv[1][2];
                           k0v=tk[1][0]; k1v=tk[1][1]; k2v=tk[1][2]; myTHR=thr1; }
            const float thrv = b0v - myTHR;
            int ck[3]; int nc = 1;
            ck[0] = k0v;
            if (b1v >= thrv) ck[nc++] = k1v;
            if (b2v >= thrv) ck[nc++] = k2v;
            if (nc == 1) {
                kid = ck[0];                            // margin proves winner
            } else {
                if (ck[0] > ck[1]) { int t = ck[0]; ck[0] = ck[1]; ck[1] = t; }
                if (nc == 3) {
                    if (ck[1] > ck[2]) { int t = ck[1]; ck[1] = ck[2]; ck[2] = t; }
                    if (ck[0] > ck[1]) { int t = ck[0]; ck[0] = ck[1]; ck[1] = t; }
                }
                const int grow = tile * MTILE + myrow;
                float4 zr[16];
                const float4* zp = (const float4*)(z + (size_t)grow * D);
                #pragma unroll
                for (int i = 0; i < 16; i++) zr[i] = zp[i];
                const float z2 = z2_of(zr);
                float best = 3.402823466e38f; kid = ck[0];
                for (int i = 0; i < nc; i++) {          // ascending k, strict <
                    float d = exact_d2(zr, z2, cb + (size_t)ck[i] * D);
                    if (d < best) { best = d; kid = ck[i]; }
                }
            }
        }

        // ---- warp-cooperative exact scan for unsafe rows (rare) ----
        unsigned need = __ballot_sync(0xffffffffu, my_unsafe);
        while (need) {
            const int src = __ffs(need) - 1;
            need &= need - 1;
            const int rl = __shfl_sync(0xffffffffu, myrow, src);
            const int grow = tile * MTILE + rl;
            float4 zr[16];
            const float4* zp = (const float4*)(z + (size_t)grow * D);
            #pragma unroll
            for (int i = 0; i < 16; i++) zr[i] = zp[i];
            const float z2 = z2_of(zr);
            float best = 3.402823466e38f; int bk = KCODES;
            for (int k = lane; k < KCODES; k += 32) {   // lane-ascending, strict <
                float d = exact_d2(zr, z2, cb + (size_t)k * D);
                if (d < best) { best = d; bk = k; }
            }
            #pragma unroll
            for (int off = 16; off; off >>= 1) {
                float ob = __shfl_xor_sync(0xffffffffu, best, off);
                int   obk = __shfl_xor_sync(0xffffffffu, bk, off);
                if (ob < best || (ob == best && obk < bk)) { best = ob; bk = obk; }
            }
            if (lane == src) kid = bk;
        }

        if (mine) kidS[myrow] = kid;
        __syncthreads();   // kidS visible; afr consumed -> A reusable

        // ---- overlapped tail: low half stages t+1, high half runs epilogue ----
        if (tid < MTILE) {
            const int next = tile + gridDim.x;
            if (next < ntiles) {
                float4 zr[16];
                const float4* zp = (const float4*)(z + (size_t)(next * MTILE + tid) * D);
                #pragma unroll
                for (int i = 0; i < 16; i++) zr[i] = zp[i];
                z2s[tid] = stage_row_fp16(smem + A_OFF + tid * 144, zr);
            }
        } else {
            const int row  = tid - MTILE;               // 0..127
            const int grow = tile * MTILE + row;
            const int k = kidS[row];
            float4 zr[16];
            const float4* zp = (const float4*)(z + (size_t)grow * D);
            #pragma unroll
            for (int i = 0; i < 16; i++) zr[i] = zp[i];
            const float4* q4 = (const float4*)(cb + (size_t)k * D);
            float4* qo = (float4*)(q_out + (size_t)grow * D);
            float lsum = 0.f;
            #pragma unroll
            for (int i = 0; i < 16; i++) {
                float4 cv = q4[i];
                float4 zv = zr[i];
                float dx = zv.x - cv.x, dy = zv.y - cv.y;
                float dz = zv.z - cv.z, dw = zv.w - cv.w;
                lsum += dx * dx + dy * dy + dz * dz + dw * dw;
                float4 o;
                o.x = zv.x + (cv.x - zv.x);   // fl(z + fl(q - z)), reference STE
                o.y = zv.y + (cv.y - zv.y);
                o.z = zv.z + (cv.z - zv.z);
                o.w = zv.w + (cv.w - zv.w);
                qo[i] = o;
            }
            if (ids_out) ids_out[grow] = (float)k;
            dsum += (double)lsum;
        }
    }

    // ---- deterministic per-CTA loss reduction ----
    __syncthreads();
    double* red = (double*)(smem + B_OFF);   // codebook region reusable now
    red[tid] = dsum;
    __syncthreads();
    if (tid == 0) {
        double s = 0.0;
        for (int i = 0; i < TPB; i++) s += red[i];
        g_partial[blockIdx.x] = s;
    }
}

// ============================================================================
// Generic fallback (round-2 kernel) for unexpected shapes
// ============================================================================
#define FTPB 256
#define ROW_PAD 68
__global__ __launch_bounds__(FTPB) void vq_ref(
    const float* __restrict__ z, const float* __restrict__ cb,
    int N, int K, float* __restrict__ q_out, float* __restrict__ ids_out)
{
    extern __shared__ float fsm[];
    float* cbs = fsm;
    float* c2  = fsm + (size_t)K * ROW_PAD;
    const int tid = threadIdx.x;
    const float4* cb4 = (const float4*)cb;
    const int nvec = K * (D / 4);
    for (int idx = tid; idx < nvec; idx += FTPB) {
        int k = idx >> 4, c = idx & 15;
        *(float4*)&cbs[k * ROW_PAD + c * 4] = cb4[idx];
    }
    __syncthreads();
    for (int k = tid; k < K; k += FTPB) {
        const float* r = &cbs[k * ROW_PAD];
        float s = 0.f;
        #pragma unroll
        for (int i = 0; i < D; i++) s += r[i] * r[i];
        c2[k] = s;
    }
    __syncthreads();
    const int row = blockIdx.x * FTPB + tid;
    float lsum = 0.f;
    if (row < N) {
        float4 zr[16];
        const float4* zp = (const float4*)(z + (size_t)row * D);
        #pragma unroll
        for (int i = 0; i < 16; i++) zr[i] = zp[i];
        float z2 = 0.f;
        #pragma unroll
        for (int i = 0; i < 16; i++)
            z2 += zr[i].x * zr[i].x + zr[i].y * zr[i].y
                + zr[i].z * zr[i].z + zr[i].w * zr[i].w;
        float best = 3.402823466e38f; int bid = 0;
        for (int k = 0; k < K; k++) {
            const float4* crow = (const float4*)&cbs[k * ROW_PAD];
            float a0 = 0.f, a1 = 0.f, a2 = 0.f, a3 = 0.f;
            #pragma unroll
            for (int i = 0; i < 16; i++) {
                float4 cv = crow[i];
                a0 += zr[i].x * cv.x; a1 += zr[i].y * cv.y;
                a2 += zr[i].z * cv.z; a3 += zr[i].w * cv.w;
            }
            float dot = (a0 + a1) + (a2 + a3);
            float d = (z2 - 2.0f * dot) + c2[k];
            if (d < best) { best = d; bid = k; }
        }
        const float4* crow = (const float4*)&cbs[bid * ROW_PAD];
        float4* qo = (float4*)(q_out + (size_t)row * D);
        #pragma unroll
        for (int i = 0; i < 16; i++) {
            float4 cv = crow[i];
            float4 zv = zr[i];
            float dx = zv.x - cv.x, dy = zv.y - cv.y;
            float dz = zv.z - cv.z, dw = zv.w - cv.w;
            lsum += dx * dx + dy * dy + dz * dz + dw * dw;
            float4 o;
            o.x = zv.x + (cv.x - zv.x); o.y = zv.y + (cv.y - zv.y);
            o.z = zv.z + (cv.z - zv.z); o.w = zv.w + (cv.w - zv.w);
            qo[i] = o;
        }
        if (ids_out) ids_out[row] = (float)bid;
    }
    #pragma unroll
    for (int off = 16; off; off >>= 1)
        lsum += __shfl_down_sync(0xffffffffu, lsum, off);
    __shared__ double wp[FTPB / 32];
    if ((tid & 31) == 0) wp[tid >> 5] = (double)lsum;
    __syncthreads();
    if (tid == 0) {
        double s = 0.0;
        #pragma unroll
        for (int w = 0; w < FTPB / 32; w++) s += wp[w];
        g_partial[blockIdx.x] = s;
    }
}

__global__ void vq_finalize(int nblocks, double inv_total, float* loss_out)
{
    __shared__ double sp[256];
    const int tid = threadIdx.x;
    double s = 0.0;
    for (int i = tid; i < nblocks; i += 256) s += g_partial[i];
    sp[tid] = s;
    __syncthreads();
    for (int off = 128; off; off >>= 1) {
        if (tid < off) sp[tid] += sp[tid + off];
        __syncthreads();
    }
    if (tid == 0) {
        double mean = sp[0] * inv_total;
        loss_out[0] = (float)(mean + 0.25 * mean);
    }
}

extern "C" void kernel_launch(void* const* d_in, const int* in_sizes, int n_in,
                              void* d_out, int out_size)
{
    const float* z  = (const float*)d_in[0];
    const float* cb = (const float*)d_in[1];
    const int N = in_sizes[0] / D;
    const int K = in_sizes[1] / D;

    float* out = (float*)d_out;
    float* q_out    = out;
    float* loss_ptr = nullptr;
    float* ids_ptr  = nullptr;
    const long base = (long)N * D;
    if ((long)out_size >= base + 1 + N) { loss_ptr = out + base; ids_ptr = out + base + 1; }
    else if ((long)out_size == base + N) { ids_ptr = out + base; }
    else if ((long)out_size == base + 1) { loss_ptr = out + base; }

    int nblocks;
    if (K == KCODES && (N % MTILE) == 0 && N > 0) {
        const int ntiles = N / MTILE;
        nblocks = ntiles < GRID_MAX ? ntiles : GRID_MAX;
        cudaFuncSetAttribute(vq_mma, cudaFuncAttributeMaxDynamicSharedMemorySize, SMEM_TOTAL);
        vq_mma<<<nblocks, TPB, SMEM_TOTAL>>>(z, cb, N, q_out, ids_ptr);
    } else {
        const size_t smem_bytes = ((size_t)K * ROW_PAD + K) * sizeof(float);
        cudaFuncSetAttribute(vq_ref, cudaFuncAttributeMaxDynamicSharedMemorySize, (int)smem_bytes);
        nblocks = (N + FTPB - 1) / FTPB;
        vq_ref<<<nblocks, FTPB, smem_bytes>>>(z, cb, N, K, q_out, ids_ptr);
    }

    if (loss_ptr) {
        double inv_total = 1.0 / ((double)N * (double)D);
        vq_finalize<<<1, 256>>>(nblocks, inv_total, loss_ptr);
    }
}